// round 16
// baseline (speedup 1.0000x reference)
#include <cuda_runtime.h>
#include <cuda_fp16.h>
#include <cstdint>
#include <math.h>

#define L_SEQ 2048
#define E_DIM 2048
#define H_NUM 16
#define D_HEAD 128
#define E3 6144

// ---------------------------------------------------------------------------
// Device-global scratch (allocation-free rule)
// ---------------------------------------------------------------------------
__device__ __align__(16) __half g_xh[L_SEQ * E_DIM];
__device__ __align__(16) __half g_wih[E3 * E_DIM];
__device__ __align__(16) __half g_woh[E_DIM * E_DIM];
__device__ __align__(16) __half g_qkvh[L_SEQ * E3];
__device__ __align__(16) __half g_ch[L_SEQ * E_DIM];
__device__ __align__(16) __half g_bh[L_SEQ * L_SEQ];   // fp16 bias matrix

__device__ __forceinline__ uint32_t smem_u32(const void* p) {
    uint32_t a;
    asm("{ .reg .u64 t; cvta.to.shared.u64 t, %1; cvt.u32.u64 %0, t; }" : "=r"(a) : "l"(p));
    return a;
}
__device__ __forceinline__ void cp_async16(uint32_t dst, const void* src) {
    asm volatile("cp.async.cg.shared.global [%0], [%1], 16;" :: "r"(dst), "l"(src));
}
__device__ __forceinline__ void cp_commit() {
    asm volatile("cp.async.commit_group;" ::: "memory");
}
__device__ __forceinline__ void cp_wait2() {
    asm volatile("cp.async.wait_group 2;" ::: "memory");
}
__device__ __forceinline__ void cp_wait1() {
    asm volatile("cp.async.wait_group 1;" ::: "memory");
}
__device__ __forceinline__ void cp_wait0() {
    asm volatile("cp.async.wait_group 0;" ::: "memory");
}
__device__ __forceinline__ void ldm_x4(uint32_t* r, uint32_t addr) {
    asm volatile("ldmatrix.sync.aligned.m8n8.x4.shared.b16 {%0,%1,%2,%3}, [%4];"
                 : "=r"(r[0]), "=r"(r[1]), "=r"(r[2]), "=r"(r[3]) : "r"(addr));
}
__device__ __forceinline__ void ldm_x4_t(uint32_t* r, uint32_t addr) {
    asm volatile("ldmatrix.sync.aligned.m8n8.x4.trans.shared.b16 {%0,%1,%2,%3}, [%4];"
                 : "=r"(r[0]), "=r"(r[1]), "=r"(r[2]), "=r"(r[3]) : "r"(addr));
}
__device__ __forceinline__ void mma_f16(float* c, const uint32_t* a, const uint32_t* b) {
    asm("mma.sync.aligned.m16n8k16.row.col.f32.f16.f16.f32 "
        "{%0,%1,%2,%3}, {%4,%5,%6,%7}, {%8,%9}, {%0,%1,%2,%3};"
        : "+f"(c[0]), "+f"(c[1]), "+f"(c[2]), "+f"(c[3])
        : "r"(a[0]), "r"(a[1]), "r"(a[2]), "r"(a[3]), "r"(b[0]), "r"(b[1]));
}
__device__ __forceinline__ uint32_t pack_h2(__half a, __half b) {
    __half2 t = __halves2half2(a, b);
    return *reinterpret_cast<uint32_t*>(&t);
}
// Hardware exp2 on the MUFU pipe. ex2.approx(-inf) = +0.
__device__ __forceinline__ float ex2(float x) {
    float y;
    asm("ex2.approx.f32 %0, %1;" : "=f"(y) : "f"(x));
    return y;
}

// ---------------------------------------------------------------------------
// fp32 -> fp16 convert
// ---------------------------------------------------------------------------
__global__ void conv_f16_kernel(const float* __restrict__ in,
                                __half* __restrict__ hi, int n4)
{
    int i = blockIdx.x * blockDim.x + threadIdx.x;
    if (i >= n4) return;
    float4 v = ((const float4*)in)[i];
    ((__half2*)hi)[2 * i]     = __halves2half2(__float2half_rn(v.x), __float2half_rn(v.y));
    ((__half2*)hi)[2 * i + 1] = __halves2half2(__float2half_rn(v.z), __float2half_rn(v.w));
}

// ---------------------------------------------------------------------------
// fp16 1-pass GEMM (unchanged from R15): CTA 128x128, 4 warps of 64x64,
// 4-stage ring, 2 CTAs/SM.
// ---------------------------------------------------------------------------
#define GM_TILE_BYTES 8192
#define GM_STAGE (2 * GM_TILE_BYTES)
#define GM_NSTAGE 4
#define GM_SMEM (GM_NSTAGE * GM_STAGE)     // 64 KB per CTA

__device__ __forceinline__ void issue_tile(uint32_t smem_tile,
                                           const __half* __restrict__ G,
                                           int row0, int k0, int K, int tid)
{
#pragma unroll
    for (int t = 0; t < 4; t++) {
        int id = tid + t * 128;
        int r  = id >> 2;
        int c  = id & 3;
        int pc = c ^ ((r >> 1) & 3);
        cp_async16(smem_tile + r * 64 + pc * 16,
                   G + (size_t)(row0 + r) * K + k0 + c * 8);
    }
}
__device__ __forceinline__ void issue_stage(uint32_t base,
                                            const __half* A, const __half* B,
                                            int m0, int n0, int k0, int K, int tid)
{
    issue_tile(base,                 A, m0, k0, K, tid);
    issue_tile(base + GM_TILE_BYTES, B, n0, k0, K, tid);
}

__global__ __launch_bounds__(128, 2) void gemm_mma(
    const __half* __restrict__ A, const __half* __restrict__ B,
    const float* __restrict__ bias, float* __restrict__ Cf,
    __half* __restrict__ Ch,
    int M, int N, int K)
{
    extern __shared__ char smc[];
    const uint32_t sb = smem_u32(smc);
    const int tid = threadIdx.x;
    const int lane = tid & 31;
    const int wid = tid >> 5;
    const int wm = wid & 1;
    const int wn = wid >> 1;
    const int m0 = blockIdx.y * 128;
    const int n0 = blockIdx.x * 128;

    const int S = K >> 5;

#pragma unroll
    for (int s = 0; s < 3; s++) {
        issue_stage(sb + s * GM_STAGE, A, B, m0, n0, s * 32, K, tid);
        cp_commit();
    }

    float acc[4][8][4];
#pragma unroll
    for (int i = 0; i < 4; i++)
#pragma unroll
        for (int j = 0; j < 8; j++)
#pragma unroll
            for (int r = 0; r < 4; r++) acc[i][j][r] = 0.f;

    const int a_r = wm * 64 + (lane & 15);
    const int a_c = (lane >> 4);
    const int s_br = (lane & 7) + ((lane >> 4) & 1) * 8;
    const int s_bc = (lane >> 3) & 1;

    for (int s = 0; s < S; s++) {
        cp_wait2();
        __syncthreads();

        if (s + 3 < S)
            issue_stage(sb + ((s + 3) & 3) * GM_STAGE, A, B,
                        m0, n0, (s + 3) * 32, K, tid);
        cp_commit();

        const uint32_t base = sb + (s & 3) * GM_STAGE;
        const uint32_t tA = base;
        const uint32_t tB = base + GM_TILE_BYTES;

#pragma unroll
        for (int ks = 0; ks < 2; ks++) {
            uint32_t ah[4][4];
#pragma unroll
            for (int mt = 0; mt < 4; mt++) {
                int r = a_r + mt * 16;
                int pc = (ks * 2 + a_c) ^ ((r >> 1) & 3);
                ldm_x4(ah[mt], tA + r * 64 + pc * 16);
            }
#pragma unroll
            for (int g = 0; g < 4; g++) {
                int r = wn * 64 + g * 16 + s_br;
                int pc = (ks * 2 + s_bc) ^ ((r >> 1) & 3);
                uint32_t th[4];
                ldm_x4(th, tB + r * 64 + pc * 16);
                uint32_t b0[2] = {th[0], th[1]}, b1[2] = {th[2], th[3]};
#pragma unroll
                for (int mt = 0; mt < 4; mt++) {
                    mma_f16(acc[mt][2 * g],     ah[mt], b0);
                    mma_f16(acc[mt][2 * g + 1], ah[mt], b1);
                }
            }
        }
    }

    const int cm = m0 + wm * 64 + (lane >> 2);
    const int cn = n0 + wn * 64 + (lane & 3) * 2;
    if (Cf) {
#pragma unroll
        for (int nt = 0; nt < 8; nt++) {
            float b0 = bias[cn + nt * 8];
            float b1 = bias[cn + nt * 8 + 1];
#pragma unroll
            for (int mt = 0; mt < 4; mt++) {
                float* r0 = Cf + (size_t)(cm + mt * 16) * N + cn + nt * 8;
                float* r1 = r0 + 8 * N;
                *(float2*)r0 = make_float2(acc[mt][nt][0] + b0, acc[mt][nt][1] + b1);
                *(float2*)r1 = make_float2(acc[mt][nt][2] + b0, acc[mt][nt][3] + b1);
            }
        }
    } else {
#pragma unroll
        for (int nt = 0; nt < 8; nt++) {
            float b0 = bias[cn + nt * 8];
            float b1 = bias[cn + nt * 8 + 1];
#pragma unroll
            for (int mt = 0; mt < 4; mt++) {
#pragma unroll
                for (int half = 0; half < 2; half++) {
                    float v0 = acc[mt][nt][2 * half + 0] + b0;
                    float v1 = acc[mt][nt][2 * half + 1] + b1;
                    size_t off = (size_t)(cm + mt * 16 + half * 8) * N + cn + nt * 8;
                    *(uint32_t*)(Ch + off) =
                        pack_h2(__float2half_rn(v0), __float2half_rn(v1));
                }
            }
        }
    }
}

// ---------------------------------------------------------------------------
// fp16 flash attention, BK=128, fp16 bias PREFETCHED before S-MMAs.
// 2-stage ring of 64KB stages; Q transient in buf0.
// ---------------------------------------------------------------------------
#define ATT_BK 128
#define ATT_STAGE 65536
#define ATT_SMEM (2 * ATT_STAGE)         // 128 KB
#define ATT_NT 16

__device__ __forceinline__ uint32_t sw_addr(uint32_t base, int r, int c) {
    return base + r * 256 + ((c ^ (r & 7)) << 4);
}
__device__ __forceinline__ void att_load_tile(uint32_t dst,
                                              const __half* __restrict__ g,
                                              int k0, int tid)
{
#pragma unroll
    for (int i = 0; i < 8; i++) {
        int id = tid + i * 256;
        int r = id >> 4;
        int c = id & 15;
        cp_async16(sw_addr(dst, r, c), g + (size_t)(k0 + r) * E3 + c * 8);
    }
}

__global__ __launch_bounds__(256, 1) void attn_tc(
    const __half* __restrict__ qkvh,
    const __half* __restrict__ biasH,
    __half* __restrict__ ch)
{
    extern __shared__ char smc[];
    const uint32_t sb = smem_u32(smc);
    const int tid = threadIdx.x;
    const int lane = tid & 31;
    const int wid = tid >> 5;
    const int h = blockIdx.y;
    const int q0 = blockIdx.x * 128;

    const __half* gKh = qkvh + E_DIM + h * D_HEAD;
    const __half* gVh = qkvh + 2 * E_DIM + h * D_HEAD;

    {
        const __half* gqh = qkvh + (size_t)q0 * E3 + h * D_HEAD;
#pragma unroll
        for (int i = 0; i < 8; i++) {
            int id = tid + i * 256;
            int r = id >> 4;
            int c = id & 15;
            cp_async16(sw_addr(sb, r, c), gqh + (size_t)r * E3 + c * 8);
        }
        cp_commit();
    }
    att_load_tile(sb + ATT_STAGE,         gKh, 0, tid);
    att_load_tile(sb + ATT_STAGE + 32768, gVh, 0, tid);
    cp_commit();

    cp_wait1();
    __syncthreads();

    uint32_t qh_f[8][4];
    {
        int r = wid * 16 + (lane & 15);
#pragma unroll
        for (int kf = 0; kf < 8; kf++) {
            int c = 2 * kf + (lane >> 4);
            ldm_x4(qh_f[kf], sw_addr(sb, r, c));
        }
    }
    __syncthreads();

    att_load_tile(sb + 0,     gKh, ATT_BK, tid);
    att_load_tile(sb + 32768, gVh, ATT_BK, tid);
    cp_commit();

    float mA = -INFINITY, mB = -INFINITY, lA = 0.f, lB = 0.f;
    float ctx[16][4];
#pragma unroll
    for (int i = 0; i < 16; i++)
#pragma unroll
        for (int j = 0; j < 4; j++) ctx[i][j] = 0.f;

    const float SCALE = 0.088388347648318447f;
    const float LOG2E = 1.4426950408889634f;
    const int rA = q0 + wid * 16 + (lane >> 2);
    const int rB = rA + 8;
    const int cb = 2 * (lane & 3);

    const int s_br = (lane & 7) + ((lane >> 4) & 1) * 8;
    const int s_bc = (lane >> 3) & 1;
    const int a_r = (lane & 15);
    const int a_c = (lane >> 4);

    const __half* bA_base = biasH + (size_t)rA * L_SEQ + cb;
    const __half* bB_base = biasH + (size_t)rB * L_SEQ + cb;

    for (int kt = 0; kt < ATT_NT; kt++) {
        if (kt < ATT_NT - 2) cp_wait1(); else cp_wait0();
        __syncthreads();
        const uint32_t buf = sb + (uint32_t)((kt + 1) & 1) * ATT_STAGE;
        const int k0 = kt * ATT_BK;

        // ---- PREFETCH fp16 bias for this tile (consumed after S-MMAs;
        //      LDG latency hidden behind the HMMA work below)
        uint32_t bfA[16], bfB[16];
#pragma unroll
        for (int nt = 0; nt < 16; nt++) {
            bfA[nt] = *(const uint32_t*)(bA_base + k0 + nt * 8);
            bfB[nt] = *(const uint32_t*)(bB_base + k0 + nt * 8);
        }

        // ---- S = scale * Qh @ Kh^T  (16 n-tiles)
        float sacc[16][4];
#pragma unroll
        for (int i = 0; i < 16; i++)
#pragma unroll
            for (int j = 0; j < 4; j++) sacc[i][j] = 0.f;

#pragma unroll
        for (int kf = 0; kf < 8; kf++) {
#pragma unroll
            for (int ng = 0; ng < 8; ng++) {
                int r = ng * 16 + s_br;
                int c = 2 * kf + s_bc;
                uint32_t th[4];
                ldm_x4(th, sw_addr(buf, r, c));
                uint32_t b0[2] = {th[0], th[1]}, b1[2] = {th[2], th[3]};
                mma_f16(sacc[2 * ng],     qh_f[kf], b0);
                mma_f16(sacc[2 * ng + 1], qh_f[kf], b1);
            }
        }

        // ---- bias (prefetched) + max
        float mxA = -INFINITY, mxB = -INFINITY;
#pragma unroll
        for (int nt = 0; nt < 16; nt++) {
            float2 bA = __half22float2(*(const __half2*)&bfA[nt]);
            float2 bB = __half22float2(*(const __half2*)&bfB[nt]);
            sacc[nt][0] = fmaf(sacc[nt][0], SCALE, bA.x);
            sacc[nt][1] = fmaf(sacc[nt][1], SCALE, bA.y);
            sacc[nt][2] = fmaf(sacc[nt][2], SCALE, bB.x);
            sacc[nt][3] = fmaf(sacc[nt][3], SCALE, bB.y);
            mxA = fmaxf(mxA, fmaxf(sacc[nt][0], sacc[nt][1]));
            mxB = fmaxf(mxB, fmaxf(sacc[nt][2], sacc[nt][3]));
        }
        mxA = fmaxf(mxA, __shfl_xor_sync(0xffffffffu, mxA, 1));
        mxA = fmaxf(mxA, __shfl_xor_sync(0xffffffffu, mxA, 2));
        mxB = fmaxf(mxB, __shfl_xor_sync(0xffffffffu, mxB, 1));
        mxB = fmaxf(mxB, __shfl_xor_sync(0xffffffffu, mxB, 2));
        float mnA = fmaxf(mA, mxA), mnB = fmaxf(mB, mxB);
        float alA = ex2((mA - mnA) * LOG2E);
        float alB = ex2((mB - mnB) * LOG2E);
        float negA = mnA * LOG2E, negB = mnB * LOG2E;
        float sumA = 0.f, sumB = 0.f;
#pragma unroll
        for (int nt = 0; nt < 16; nt++) {
            sacc[nt][0] = ex2(fmaf(sacc[nt][0], LOG2E, -negA));
            sacc[nt][1] = ex2(fmaf(sacc[nt][1], LOG2E, -negA));
            sacc[nt][2] = ex2(fmaf(sacc[nt][2], LOG2E, -negB));
            sacc[nt][3] = ex2(fmaf(sacc[nt][3], LOG2E, -negB));
            sumA += sacc[nt][0] + sacc[nt][1];
            sumB += sacc[nt][2] + sacc[nt][3];
        }
        sumA += __shfl_xor_sync(0xffffffffu, sumA, 1);
        sumA += __shfl_xor_sync(0xffffffffu, sumA, 2);
        sumB += __shfl_xor_sync(0xffffffffu, sumB, 1);
        sumB += __shfl_xor_sync(0xffffffffu, sumB, 2);
        lA = lA * alA + sumA;
        lB = lB * alB + sumB;
        mA = mnA; mB = mnB;
#pragma unroll
        for (int nt = 0; nt < 16; nt++) {
            ctx[nt][0] *= alA; ctx[nt][1] *= alA;
            ctx[nt][2] *= alB; ctx[nt][3] *= alB;
        }

        uint32_t pah[8][4];
#pragma unroll
        for (int kb = 0; kb < 8; kb++) {
#pragma unroll
            for (int half = 0; half < 2; half++) {
#pragma unroll
                for (int sub = 0; sub < 2; sub++) {
                    float p0 = sacc[2 * kb + sub][2 * half + 0];
                    float p1 = sacc[2 * kb + sub][2 * half + 1];
                    pah[kb][sub * 2 + half] =
                        pack_h2(__float2half_rn(p0), __float2half_rn(p1));
                }
            }
        }

#pragma unroll
        for (int kb = 0; kb < 8; kb++) {
#pragma unroll
            for (int db = 0; db < 8; db++) {
                int r = kb * 16 + a_r;
                int c = 2 * db + a_c;
                uint32_t th[4];
                ldm_x4_t(th, sw_addr(buf + 32768, r, c));
                uint32_t b0[2] = {th[0], th[1]}, b1[2] = {th[2], th[3]};
                mma_f16(ctx[2 * db],     pah[kb], b0);
                mma_f16(ctx[2 * db + 1], pah[kb], b1);
            }
        }

        __syncthreads();
        if (kt + 2 < ATT_NT) {
            const uint32_t nbuf = sb + (uint32_t)((kt + 1) & 1) * ATT_STAGE;
            const int nk0 = (kt + 2) * ATT_BK;
            att_load_tile(nbuf + 0,     gKh, nk0, tid);
            att_load_tile(nbuf + 32768, gVh, nk0, tid);
            cp_commit();
        } else {
            cp_commit();
        }
    }

    float iA = 1.f / lA, iB = 1.f / lB;
#pragma unroll
    for (int nt = 0; nt < 16; nt++) {
        int col = h * D_HEAD + nt * 8 + cb;
        float v0 = ctx[nt][0] * iA, v1 = ctx[nt][1] * iA;
        float v2 = ctx[nt][2] * iB, v3 = ctx[nt][3] * iB;
        *(uint32_t*)(ch + (size_t)rA * E_DIM + col) =
            pack_h2(__float2half_rn(v0), __float2half_rn(v1));
        *(uint32_t*)(ch + (size_t)rB * E_DIM + col) =
            pack_h2(__float2half_rn(v2), __float2half_rn(v3));
    }
}

// ---------------------------------------------------------------------------
extern "C" void kernel_launch(void* const* d_in, const int* in_sizes, int n_in,
                              void* d_out, int out_size)
{
    const float* x     = (const float*)d_in[0];
    const float* biasM = (const float*)d_in[1];
    const float* w_in  = (const float*)d_in[2];
    const float* b_in  = (const float*)d_in[3];
    const float* w_out = (const float*)d_in[4];
    const float* b_out = (const float*)d_in[5];
    float* out = (float*)d_out;

    __half *xh, *wih, *woh, *qkvh, *ch, *bh;
    cudaGetSymbolAddress((void**)&xh, g_xh);
    cudaGetSymbolAddress((void**)&wih, g_wih);
    cudaGetSymbolAddress((void**)&woh, g_woh);
    cudaGetSymbolAddress((void**)&qkvh, g_qkvh);
    cudaGetSymbolAddress((void**)&ch, g_ch);
    cudaGetSymbolAddress((void**)&bh, g_bh);

    cudaFuncSetAttribute(gemm_mma, cudaFuncAttributeMaxDynamicSharedMemorySize, GM_SMEM);
    cudaFuncSetAttribute(attn_tc, cudaFuncAttributeMaxDynamicSharedMemorySize, ATT_SMEM);

    {
        int n4 = (L_SEQ * E_DIM) / 4;
        conv_f16_kernel<<<(n4 + 255) / 256, 256>>>(x, xh, n4);
        int w4 = (E3 * E_DIM) / 4;
        conv_f16_kernel<<<(w4 + 255) / 256, 256>>>(w_in, wih, w4);
        int o4 = (E_DIM * E_DIM) / 4;
        conv_f16_kernel<<<(o4 + 255) / 256, 256>>>(w_out, woh, o4);
        int b4 = (L_SEQ * L_SEQ) / 4;
        conv_f16_kernel<<<(b4 + 255) / 256, 256>>>(biasM, bh, b4);
    }

    // 1) QKV projection -> fp16   [2048, 6144]
    gemm_mma<<<dim3(E3 / 128, L_SEQ / 128), 128, GM_SMEM>>>(
        xh, wih, b_in, nullptr, qkvh, L_SEQ, E3, E_DIM);

    // 2) fp16 flash attention (BK=128, prefetched fp16 bias) -> fp16 ctx
    attn_tc<<<dim3(L_SEQ / 128, H_NUM), 256, ATT_SMEM>>>(
        qkvh, bh, ch);

    // 3) out projection -> fp32 output   [2048, 2048]
    gemm_mma<<<dim3(E_DIM / 128, L_SEQ / 128), 128, GM_SMEM>>>(
        ch, woh, b_out, out, nullptr, L_SEQ, E_DIM, E_DIM);
}

// round 17
// speedup vs baseline: 1.0245x; 1.0245x over previous
#include <cuda_runtime.h>
#include <cuda_fp16.h>
#include <cstdint>
#include <math.h>

#define L_SEQ 2048
#define E_DIM 2048
#define H_NUM 16
#define D_HEAD 128
#define E3 6144

// ---------------------------------------------------------------------------
// Device-global scratch (allocation-free rule)
// ---------------------------------------------------------------------------
__device__ __align__(16) __half g_xh[L_SEQ * E_DIM];
__device__ __align__(16) __half g_wih[E3 * E_DIM];
__device__ __align__(16) __half g_woh[E_DIM * E_DIM];
__device__ __align__(16) __half g_qkvh[L_SEQ * E3];
__device__ __align__(16) __half g_ch[L_SEQ * E_DIM];

__device__ __forceinline__ uint32_t smem_u32(const void* p) {
    uint32_t a;
    asm("{ .reg .u64 t; cvta.to.shared.u64 t, %1; cvt.u32.u64 %0, t; }" : "=r"(a) : "l"(p));
    return a;
}
__device__ __forceinline__ void cp_async16(uint32_t dst, const void* src) {
    asm volatile("cp.async.cg.shared.global [%0], [%1], 16;" :: "r"(dst), "l"(src));
}
__device__ __forceinline__ void cp_commit() {
    asm volatile("cp.async.commit_group;" ::: "memory");
}
__device__ __forceinline__ void cp_wait2() {
    asm volatile("cp.async.wait_group 2;" ::: "memory");
}
__device__ __forceinline__ void cp_wait1() {
    asm volatile("cp.async.wait_group 1;" ::: "memory");
}
__device__ __forceinline__ void cp_wait0() {
    asm volatile("cp.async.wait_group 0;" ::: "memory");
}
__device__ __forceinline__ void ldm_x4(uint32_t* r, uint32_t addr) {
    asm volatile("ldmatrix.sync.aligned.m8n8.x4.shared.b16 {%0,%1,%2,%3}, [%4];"
                 : "=r"(r[0]), "=r"(r[1]), "=r"(r[2]), "=r"(r[3]) : "r"(addr));
}
__device__ __forceinline__ void ldm_x4_t(uint32_t* r, uint32_t addr) {
    asm volatile("ldmatrix.sync.aligned.m8n8.x4.trans.shared.b16 {%0,%1,%2,%3}, [%4];"
                 : "=r"(r[0]), "=r"(r[1]), "=r"(r[2]), "=r"(r[3]) : "r"(addr));
}
__device__ __forceinline__ void mma_f16(float* c, const uint32_t* a, const uint32_t* b) {
    asm("mma.sync.aligned.m16n8k16.row.col.f32.f16.f16.f32 "
        "{%0,%1,%2,%3}, {%4,%5,%6,%7}, {%8,%9}, {%0,%1,%2,%3};"
        : "+f"(c[0]), "+f"(c[1]), "+f"(c[2]), "+f"(c[3])
        : "r"(a[0]), "r"(a[1]), "r"(a[2]), "r"(a[3]), "r"(b[0]), "r"(b[1]));
}
__device__ __forceinline__ uint32_t pack_h2(__half a, __half b) {
    __half2 t = __halves2half2(a, b);
    return *reinterpret_cast<uint32_t*>(&t);
}
// Hardware exp2 on the MUFU pipe. ex2.approx(-inf) = +0.
__device__ __forceinline__ float ex2(float x) {
    float y;
    asm("ex2.approx.f32 %0, %1;" : "=f"(y) : "f"(x));
    return y;
}

// ---------------------------------------------------------------------------
// fp32 -> fp16 convert, 4 independent float4s per thread (MLP=4).
// All callers pass n4 divisible by 1024, so no tail predication needed.
// ---------------------------------------------------------------------------
__global__ void conv_f16_kernel(const float* __restrict__ in,
                                __half* __restrict__ hi, int n4)
{
    int i0 = blockIdx.x * (blockDim.x * 4) + threadIdx.x;
    float4 v[4];
#pragma unroll
    for (int j = 0; j < 4; j++)
        v[j] = ((const float4*)in)[i0 + j * blockDim.x];
#pragma unroll
    for (int j = 0; j < 4; j++) {
        int idx = i0 + j * blockDim.x;
        ((__half2*)hi)[2 * idx] =
            __halves2half2(__float2half_rn(v[j].x), __float2half_rn(v[j].y));
        ((__half2*)hi)[2 * idx + 1] =
            __halves2half2(__float2half_rn(v[j].z), __float2half_rn(v[j].w));
    }
}

// ---------------------------------------------------------------------------
// fp16 1-pass GEMM (unchanged from R15): CTA 128x128, 4 warps of 64x64,
// 4-stage ring, 2 CTAs/SM.
// ---------------------------------------------------------------------------
#define GM_TILE_BYTES 8192
#define GM_STAGE (2 * GM_TILE_BYTES)
#define GM_NSTAGE 4
#define GM_SMEM (GM_NSTAGE * GM_STAGE)     // 64 KB per CTA

__device__ __forceinline__ void issue_tile(uint32_t smem_tile,
                                           const __half* __restrict__ G,
                                           int row0, int k0, int K, int tid)
{
#pragma unroll
    for (int t = 0; t < 4; t++) {
        int id = tid + t * 128;
        int r  = id >> 2;
        int c  = id & 3;
        int pc = c ^ ((r >> 1) & 3);
        cp_async16(smem_tile + r * 64 + pc * 16,
                   G + (size_t)(row0 + r) * K + k0 + c * 8);
    }
}
__device__ __forceinline__ void issue_stage(uint32_t base,
                                            const __half* A, const __half* B,
                                            int m0, int n0, int k0, int K, int tid)
{
    issue_tile(base,                 A, m0, k0, K, tid);
    issue_tile(base + GM_TILE_BYTES, B, n0, k0, K, tid);
}

__global__ __launch_bounds__(128, 2) void gemm_mma(
    const __half* __restrict__ A, const __half* __restrict__ B,
    const float* __restrict__ bias, float* __restrict__ Cf,
    __half* __restrict__ Ch,
    int M, int N, int K)
{
    extern __shared__ char smc[];
    const uint32_t sb = smem_u32(smc);
    const int tid = threadIdx.x;
    const int lane = tid & 31;
    const int wid = tid >> 5;
    const int wm = wid & 1;
    const int wn = wid >> 1;
    const int m0 = blockIdx.y * 128;
    const int n0 = blockIdx.x * 128;

    const int S = K >> 5;

#pragma unroll
    for (int s = 0; s < 3; s++) {
        issue_stage(sb + s * GM_STAGE, A, B, m0, n0, s * 32, K, tid);
        cp_commit();
    }

    float acc[4][8][4];
#pragma unroll
    for (int i = 0; i < 4; i++)
#pragma unroll
        for (int j = 0; j < 8; j++)
#pragma unroll
            for (int r = 0; r < 4; r++) acc[i][j][r] = 0.f;

    const int a_r = wm * 64 + (lane & 15);
    const int a_c = (lane >> 4);
    const int s_br = (lane & 7) + ((lane >> 4) & 1) * 8;
    const int s_bc = (lane >> 3) & 1;

    for (int s = 0; s < S; s++) {
        cp_wait2();
        __syncthreads();

        if (s + 3 < S)
            issue_stage(sb + ((s + 3) & 3) * GM_STAGE, A, B,
                        m0, n0, (s + 3) * 32, K, tid);
        cp_commit();

        const uint32_t base = sb + (s & 3) * GM_STAGE;
        const uint32_t tA = base;
        const uint32_t tB = base + GM_TILE_BYTES;

#pragma unroll
        for (int ks = 0; ks < 2; ks++) {
            uint32_t ah[4][4];
#pragma unroll
            for (int mt = 0; mt < 4; mt++) {
                int r = a_r + mt * 16;
                int pc = (ks * 2 + a_c) ^ ((r >> 1) & 3);
                ldm_x4(ah[mt], tA + r * 64 + pc * 16);
            }
#pragma unroll
            for (int g = 0; g < 4; g++) {
                int r = wn * 64 + g * 16 + s_br;
                int pc = (ks * 2 + s_bc) ^ ((r >> 1) & 3);
                uint32_t th[4];
                ldm_x4(th, tB + r * 64 + pc * 16);
                uint32_t b0[2] = {th[0], th[1]}, b1[2] = {th[2], th[3]};
#pragma unroll
                for (int mt = 0; mt < 4; mt++) {
                    mma_f16(acc[mt][2 * g],     ah[mt], b0);
                    mma_f16(acc[mt][2 * g + 1], ah[mt], b1);
                }
            }
        }
    }

    const int cm = m0 + wm * 64 + (lane >> 2);
    const int cn = n0 + wn * 64 + (lane & 3) * 2;
    if (Cf) {
#pragma unroll
        for (int nt = 0; nt < 8; nt++) {
            float b0 = bias[cn + nt * 8];
            float b1 = bias[cn + nt * 8 + 1];
#pragma unroll
            for (int mt = 0; mt < 4; mt++) {
                float* r0 = Cf + (size_t)(cm + mt * 16) * N + cn + nt * 8;
                float* r1 = r0 + 8 * N;
                *(float2*)r0 = make_float2(acc[mt][nt][0] + b0, acc[mt][nt][1] + b1);
                *(float2*)r1 = make_float2(acc[mt][nt][2] + b0, acc[mt][nt][3] + b1);
            }
        }
    } else {
#pragma unroll
        for (int nt = 0; nt < 8; nt++) {
            float b0 = bias[cn + nt * 8];
            float b1 = bias[cn + nt * 8 + 1];
#pragma unroll
            for (int mt = 0; mt < 4; mt++) {
#pragma unroll
                for (int half = 0; half < 2; half++) {
                    float v0 = acc[mt][nt][2 * half + 0] + b0;
                    float v1 = acc[mt][nt][2 * half + 1] + b1;
                    size_t off = (size_t)(cm + mt * 16 + half * 8) * N + cn + nt * 8;
                    *(uint32_t*)(Ch + off) =
                        pack_h2(__float2half_rn(v0), __float2half_rn(v1));
                }
            }
        }
    }
}

// ---------------------------------------------------------------------------
// fp16 flash attention, BK=128 (exact R15 config — best measured).
// 2-stage ring of 64KB stages; Q transient in buf0.
// ---------------------------------------------------------------------------
#define ATT_BK 128
#define ATT_STAGE 65536
#define ATT_SMEM (2 * ATT_STAGE)         // 128 KB
#define ATT_NT 16

__device__ __forceinline__ uint32_t sw_addr(uint32_t base, int r, int c) {
    return base + r * 256 + ((c ^ (r & 7)) << 4);
}
__device__ __forceinline__ void att_load_tile(uint32_t dst,
                                              const __half* __restrict__ g,
                                              int k0, int tid)
{
#pragma unroll
    for (int i = 0; i < 8; i++) {
        int id = tid + i * 256;
        int r = id >> 4;
        int c = id & 15;
        cp_async16(sw_addr(dst, r, c), g + (size_t)(k0 + r) * E3 + c * 8);
    }
}

__global__ __launch_bounds__(256, 1) void attn_tc(
    const __half* __restrict__ qkvh,
    const float* __restrict__ biasM,
    __half* __restrict__ ch)
{
    extern __shared__ char smc[];
    const uint32_t sb = smem_u32(smc);
    const int tid = threadIdx.x;
    const int lane = tid & 31;
    const int wid = tid >> 5;
    const int h = blockIdx.y;
    const int q0 = blockIdx.x * 128;

    const __half* gKh = qkvh + E_DIM + h * D_HEAD;
    const __half* gVh = qkvh + 2 * E_DIM + h * D_HEAD;

    {
        const __half* gqh = qkvh + (size_t)q0 * E3 + h * D_HEAD;
#pragma unroll
        for (int i = 0; i < 8; i++) {
            int id = tid + i * 256;
            int r = id >> 4;
            int c = id & 15;
            cp_async16(sw_addr(sb, r, c), gqh + (size_t)r * E3 + c * 8);
        }
        cp_commit();
    }
    att_load_tile(sb + ATT_STAGE,         gKh, 0, tid);
    att_load_tile(sb + ATT_STAGE + 32768, gVh, 0, tid);
    cp_commit();

    cp_wait1();
    __syncthreads();

    uint32_t qh_f[8][4];
    {
        int r = wid * 16 + (lane & 15);
#pragma unroll
        for (int kf = 0; kf < 8; kf++) {
            int c = 2 * kf + (lane >> 4);
            ldm_x4(qh_f[kf], sw_addr(sb, r, c));
        }
    }
    __syncthreads();

    att_load_tile(sb + 0,     gKh, ATT_BK, tid);
    att_load_tile(sb + 32768, gVh, ATT_BK, tid);
    cp_commit();

    float mA = -INFINITY, mB = -INFINITY, lA = 0.f, lB = 0.f;
    float ctx[16][4];
#pragma unroll
    for (int i = 0; i < 16; i++)
#pragma unroll
        for (int j = 0; j < 4; j++) ctx[i][j] = 0.f;

    const float SCALE = 0.088388347648318447f;
    const float LOG2E = 1.4426950408889634f;
    const int rA = q0 + wid * 16 + (lane >> 2);
    const int rB = rA + 8;
    const int cb = 2 * (lane & 3);

    const int s_br = (lane & 7) + ((lane >> 4) & 1) * 8;
    const int s_bc = (lane >> 3) & 1;
    const int a_r = (lane & 15);
    const int a_c = (lane >> 4);

    for (int kt = 0; kt < ATT_NT; kt++) {
        if (kt < ATT_NT - 2) cp_wait1(); else cp_wait0();
        __syncthreads();
        const uint32_t buf = sb + (uint32_t)((kt + 1) & 1) * ATT_STAGE;
        const int k0 = kt * ATT_BK;

        float sacc[16][4];
#pragma unroll
        for (int i = 0; i < 16; i++)
#pragma unroll
            for (int j = 0; j < 4; j++) sacc[i][j] = 0.f;

#pragma unroll
        for (int kf = 0; kf < 8; kf++) {
#pragma unroll
            for (int ng = 0; ng < 8; ng++) {
                int r = ng * 16 + s_br;
                int c = 2 * kf + s_bc;
                uint32_t th[4];
                ldm_x4(th, sw_addr(buf, r, c));
                uint32_t b0[2] = {th[0], th[1]}, b1[2] = {th[2], th[3]};
                mma_f16(sacc[2 * ng],     qh_f[kf], b0);
                mma_f16(sacc[2 * ng + 1], qh_f[kf], b1);
            }
        }

        float mxA = -INFINITY, mxB = -INFINITY;
#pragma unroll
        for (int nt = 0; nt < 16; nt++) {
            float2 bA = *(const float2*)(biasM + (size_t)rA * L_SEQ + k0 + nt * 8 + cb);
            float2 bB = *(const float2*)(biasM + (size_t)rB * L_SEQ + k0 + nt * 8 + cb);
            sacc[nt][0] = fmaf(sacc[nt][0], SCALE, bA.x);
            sacc[nt][1] = fmaf(sacc[nt][1], SCALE, bA.y);
            sacc[nt][2] = fmaf(sacc[nt][2], SCALE, bB.x);
            sacc[nt][3] = fmaf(sacc[nt][3], SCALE, bB.y);
            mxA = fmaxf(mxA, fmaxf(sacc[nt][0], sacc[nt][1]));
            mxB = fmaxf(mxB, fmaxf(sacc[nt][2], sacc[nt][3]));
        }
        mxA = fmaxf(mxA, __shfl_xor_sync(0xffffffffu, mxA, 1));
        mxA = fmaxf(mxA, __shfl_xor_sync(0xffffffffu, mxA, 2));
        mxB = fmaxf(mxB, __shfl_xor_sync(0xffffffffu, mxB, 1));
        mxB = fmaxf(mxB, __shfl_xor_sync(0xffffffffu, mxB, 2));
        float mnA = fmaxf(mA, mxA), mnB = fmaxf(mB, mxB);
        float alA = ex2((mA - mnA) * LOG2E);
        float alB = ex2((mB - mnB) * LOG2E);
        float negA = mnA * LOG2E, negB = mnB * LOG2E;
        float sumA = 0.f, sumB = 0.f;
#pragma unroll
        for (int nt = 0; nt < 16; nt++) {
            sacc[nt][0] = ex2(fmaf(sacc[nt][0], LOG2E, -negA));
            sacc[nt][1] = ex2(fmaf(sacc[nt][1], LOG2E, -negA));
            sacc[nt][2] = ex2(fmaf(sacc[nt][2], LOG2E, -negB));
            sacc[nt][3] = ex2(fmaf(sacc[nt][3], LOG2E, -negB));
            sumA += sacc[nt][0] + sacc[nt][1];
            sumB += sacc[nt][2] + sacc[nt][3];
        }
        sumA += __shfl_xor_sync(0xffffffffu, sumA, 1);
        sumA += __shfl_xor_sync(0xffffffffu, sumA, 2);
        sumB += __shfl_xor_sync(0xffffffffu, sumB, 1);
        sumB += __shfl_xor_sync(0xffffffffu, sumB, 2);
        lA = lA * alA + sumA;
        lB = lB * alB + sumB;
        mA = mnA; mB = mnB;
#pragma unroll
        for (int nt = 0; nt < 16; nt++) {
            ctx[nt][0] *= alA; ctx[nt][1] *= alA;
            ctx[nt][2] *= alB; ctx[nt][3] *= alB;
        }

        uint32_t pah[8][4];
#pragma unroll
        for (int kb = 0; kb < 8; kb++) {
#pragma unroll
            for (int half = 0; half < 2; half++) {
#pragma unroll
                for (int sub = 0; sub < 2; sub++) {
                    float p0 = sacc[2 * kb + sub][2 * half + 0];
                    float p1 = sacc[2 * kb + sub][2 * half + 1];
                    pah[kb][sub * 2 + half] =
                        pack_h2(__float2half_rn(p0), __float2half_rn(p1));
                }
            }
        }

#pragma unroll
        for (int kb = 0; kb < 8; kb++) {
#pragma unroll
            for (int db = 0; db < 8; db++) {
                int r = kb * 16 + a_r;
                int c = 2 * db + a_c;
                uint32_t th[4];
                ldm_x4_t(th, sw_addr(buf + 32768, r, c));
                uint32_t b0[2] = {th[0], th[1]}, b1[2] = {th[2], th[3]};
                mma_f16(ctx[2 * db],     pah[kb], b0);
                mma_f16(ctx[2 * db + 1], pah[kb], b1);
            }
        }

        __syncthreads();
        if (kt + 2 < ATT_NT) {
            const uint32_t nbuf = sb + (uint32_t)((kt + 1) & 1) * ATT_STAGE;
            const int nk0 = (kt + 2) * ATT_BK;
            att_load_tile(nbuf + 0,     gKh, nk0, tid);
            att_load_tile(nbuf + 32768, gVh, nk0, tid);
            cp_commit();
        } else {
            cp_commit();
        }
    }

    float iA = 1.f / lA, iB = 1.f / lB;
#pragma unroll
    for (int nt = 0; nt < 16; nt++) {
        int col = h * D_HEAD + nt * 8 + cb;
        float v0 = ctx[nt][0] * iA, v1 = ctx[nt][1] * iA;
        float v2 = ctx[nt][2] * iB, v3 = ctx[nt][3] * iB;
        *(uint32_t*)(ch + (size_t)rA * E_DIM + col) =
            pack_h2(__float2half_rn(v0), __float2half_rn(v1));
        *(uint32_t*)(ch + (size_t)rB * E_DIM + col) =
            pack_h2(__float2half_rn(v2), __float2half_rn(v3));
    }
}

// ---------------------------------------------------------------------------
extern "C" void kernel_launch(void* const* d_in, const int* in_sizes, int n_in,
                              void* d_out, int out_size)
{
    const float* x     = (const float*)d_in[0];
    const float* biasM = (const float*)d_in[1];
    const float* w_in  = (const float*)d_in[2];
    const float* b_in  = (const float*)d_in[3];
    const float* w_out = (const float*)d_in[4];
    const float* b_out = (const float*)d_in[5];
    float* out = (float*)d_out;

    __half *xh, *wih, *woh, *qkvh, *ch;
    cudaGetSymbolAddress((void**)&xh, g_xh);
    cudaGetSymbolAddress((void**)&wih, g_wih);
    cudaGetSymbolAddress((void**)&woh, g_woh);
    cudaGetSymbolAddress((void**)&qkvh, g_qkvh);
    cudaGetSymbolAddress((void**)&ch, g_ch);

    cudaFuncSetAttribute(gemm_mma, cudaFuncAttributeMaxDynamicSharedMemorySize, GM_SMEM);
    cudaFuncSetAttribute(attn_tc, cudaFuncAttributeMaxDynamicSharedMemorySize, ATT_SMEM);

    {
        int n4 = (L_SEQ * E_DIM) / 4;      // 1048576, /1024 = 1024 blocks
        conv_f16_kernel<<<n4 / 1024, 256>>>(x, xh, n4);
        int w4 = (E3 * E_DIM) / 4;         // 3145728
        conv_f16_kernel<<<w4 / 1024, 256>>>(w_in, wih, w4);
        int o4 = (E_DIM * E_DIM) / 4;      // 1048576
        conv_f16_kernel<<<o4 / 1024, 256>>>(w_out, woh, o4);
    }

    // 1) QKV projection -> fp16   [2048, 6144]
    gemm_mma<<<dim3(E3 / 128, L_SEQ / 128), 128, GM_SMEM>>>(
        xh, wih, b_in, nullptr, qkvh, L_SEQ, E3, E_DIM);

    // 2) fp16 flash attention (BK=128) -> fp16 ctx
    attn_tc<<<dim3(L_SEQ / 128, H_NUM), 256, ATT_SMEM>>>(
        qkvh, biasM, ch);

    // 3) out projection -> fp32 output   [2048, 2048]
    gemm_mma<<<dim3(E_DIM / 128, L_SEQ / 128), 128, GM_SMEM>>>(
        ch, woh, b_out, out, nullptr, L_SEQ, E_DIM, E_DIM);
}